// round 15
// baseline (speedup 1.0000x reference)
#include <cuda_runtime.h>
#include <cstdint>

#define F        128
#define TM       64
#define NTHREADS 256
#define NRBF     20
#define RSTR     136   // row stride (floats): == 8 mod 32 -> conflict-free fragment STS/LDS
#define MAXE     524288
#define MAXN     16384

// smem offsets in FLOATS
#define OFF_S    0            // s tile [64][136]; later reused as sr stash   8704
#define OFF_P    8704         // stash buf [64][136]                          8704
#define OFF_RBF  17408        // rbf [64][20]                                 1280
#define OFF_IDX  18688        // 64 ints (node per row, -1 invalid)
#define OFF_EID  18752        // 64 ints (edge id per row, -1 invalid)
#define OFF_RN   18816        // 64*4 floats
#define OFF_G    19072        // 1 float
#define SMEM_FLOATS 19076
#define SMEM_BYTES  (SMEM_FLOATS * 4)

__device__ float g_part[512];
__device__ int   g_cnt[MAXN];
__device__ int   g_off[MAXN];
__device__ int   g_perm[MAXE];
// fragment-major packed weights (built once per launch)
//   wt_phi[((c*16 + ks)*16 + ntile)*32 + lane] = {W[k][c*128+n], W[k+4][c*128+n]}
__device__ uint2 wt_phi[3 * 16 * 16 * 32];
__device__ uint2 wt_ww [3 * 3 * 16 * 32];

static __device__ __forceinline__ uint32_t to_tf32(float x){
  uint32_t t;
  asm("cvt.rna.tf32.f32 %0, %1;" : "=r"(t) : "f"(x));
  return t;
}
static __device__ __forceinline__ void mma8(float c[4], uint32_t a0, uint32_t a1,
    uint32_t a2, uint32_t a3, uint32_t b0, uint32_t b1){
  asm volatile("mma.sync.aligned.m16n8k8.row.col.f32.tf32.tf32.f32 "
    "{%0,%1,%2,%3}, {%4,%5,%6,%7}, {%8,%9}, {%0,%1,%2,%3};"
    : "+f"(c[0]), "+f"(c[1]), "+f"(c[2]), "+f"(c[3])
    : "r"(a0), "r"(a1), "r"(a2), "r"(a3), "r"(b0), "r"(b1));
}
static __device__ __forceinline__ void red4(float* p, float a, float b, float c, float d){
  asm volatile("red.global.add.v4.f32 [%0], {%1, %2, %3, %4};"
               :: "l"(p), "f"(a), "f"(b), "f"(c), "f"(d) : "memory");
}

// ---- launch 1: zero output + node counters ----
__global__ void zero_kernel(float4* __restrict__ out4, int nout4, int N){
  const int gtid = blockIdx.x * blockDim.x + threadIdx.x;
  const int gstr = gridDim.x * blockDim.x;
  for (int i = gtid; i < nout4; i += gstr)
    out4[i] = make_float4(0.f, 0.f, 0.f, 0.f);
  for (int i = gtid; i < N; i += gstr)
    g_cnt[i] = 0;
}

// ---- launch 2: pack weights fragment-major + frobenius partials ----
__global__ void prep_w_kernel(const float* __restrict__ Wp_g,
                              const float* __restrict__ Ww_g,
                              const float* __restrict__ r, int n){
  const int gtid = blockIdx.x * blockDim.x + threadIdx.x;
  const int gstr = gridDim.x * blockDim.x;
  for (int i = gtid; i < 3*16*16*32; i += gstr){
    int l = i & 31, t = (i >> 5) & 15, ks = (i >> 9) & 15, c = i >> 13;
    int qr = l >> 2, kb = l & 3;
    int nn = t*8 + qr, k = ks*8 + kb;
    uint2 val;
    val.x = to_tf32(Wp_g[(size_t)k    *384 + c*128 + nn]);
    val.y = to_tf32(Wp_g[(size_t)(k+4)*384 + c*128 + nn]);
    wt_phi[i] = val;
  }
  for (int i = gtid; i < 3*3*16*32; i += gstr){
    int l = i & 31, t = (i >> 5) & 15, rr = i >> 9;   // rr = c*3 + ks
    int ks = rr % 3, c = rr / 3;
    int qr = l >> 2, kb = l & 3;
    int nn = t*8 + qr, k = ks*8 + kb;
    uint2 val;
    val.x = to_tf32(Ww_g[(size_t)k*384 + c*128 + nn]);
    val.y = (k + 4 < NRBF) ? to_tf32(Ww_g[(size_t)(k+4)*384 + c*128 + nn]) : 0u;
    wt_ww[i] = val;
  }
  float s = 0.f;
  for (int i = gtid; i < n; i += gstr){
    float x = r[i];
    s = fmaf(x, x, s);
  }
  #pragma unroll
  for (int o = 16; o > 0; o >>= 1) s += __shfl_xor_sync(0xffffffffu, s, o);
  __shared__ float ws[8];
  int lane = threadIdx.x & 31, w = threadIdx.x >> 5;
  if (lane == 0) ws[w] = s;
  __syncthreads();
  if (threadIdx.x < 32){
    s = (threadIdx.x < 8) ? ws[threadIdx.x] : 0.f;
    #pragma unroll
    for (int o = 4; o > 0; o >>= 1) s += __shfl_xor_sync(0xffffffffu, s, o);
    if (threadIdx.x == 0) g_part[blockIdx.x] = s;
  }
}

// ---- launch 3: histogram ----
__global__ void hist_kernel(const int* __restrict__ idx_g, int E){
  const int gtid = blockIdx.x * blockDim.x + threadIdx.x;
  const int gstr = gridDim.x * blockDim.x;
  for (int e = gtid; e < E; e += gstr)
    atomicAdd(&g_cnt[idx_g[e]], 1);
}

// ---- launch 4: exclusive scan (single block) ----
__global__ void scan_kernel(int N){
  const int tid = threadIdx.x;
  const int chunk = (N + 255) >> 8;
  int s0 = min(tid * chunk, N), e0 = min(s0 + chunk, N);
  int sum = 0;
  for (int i = s0; i < e0; i++) sum += g_cnt[i];
  int lane = tid & 31, w = tid >> 5;
  int x = sum;
  #pragma unroll
  for (int o = 1; o < 32; o <<= 1){
    int y = __shfl_up_sync(0xffffffffu, x, o);
    if (lane >= o) x += y;
  }
  __shared__ int wsum[8];
  if (lane == 31) wsum[w] = x;
  __syncthreads();
  int base = 0;
  for (int i = 0; i < w; i++) base += wsum[i];
  int off = base + x - sum;     // exclusive prefix
  for (int i = s0; i < e0; i++){
    int c = g_cnt[i];
    g_off[i] = off;             // fill cursor
    off += c;
  }
}

// ---- launch 5: scatter edges into node-sorted order ----
__global__ void scatter_kernel(const int* __restrict__ idx_g, int E){
  const int gtid = blockIdx.x * blockDim.x + threadIdx.x;
  const int gstr = gridDim.x * blockDim.x;
  for (int e = gtid; e < E; e += gstr){
    int pos = atomicAdd(&g_off[idx_g[e]], 1);
    g_perm[pos] = e;
  }
}

// compute chunk c, gate.
// STASH_S == 0: stash gated output inline into OFF_P.
// STASH_S == 1: hold gated output in regs, __syncthreads (s tile dead), stash into OFF_S.
template<int STASH_S>
static __device__ __forceinline__ void run_chunk(
    const uint32_t* __restrict__ su, float* __restrict__ smf,
    int tid, int c,
    const float* __restrict__ bphi_g, const float* __restrict__ bw_g)
{
  const int wid  = tid >> 5;
  const int lane = tid & 31;
  const int mg   = wid >> 1;
  const int nq   = wid & 1;
  const int qr   = lane >> 2;
  const int kb   = lane & 3;
  const int rA0  = mg * 16 + qr;
  const int nb   = nq * 64;

  float acc[8][4];
  #pragma unroll
  for (int nt = 0; nt < 8; nt++){
    acc[nt][0]=0.f; acc[nt][1]=0.f; acc[nt][2]=0.f; acc[nt][3]=0.f;
  }

  const uint2* wtp = wt_phi + ((size_t)c*16*16 + nq*8)*32 + lane;
  #pragma unroll 4
  for (int ks = 0; ks < 16; ks++){
    const int kp = ks * 8 + kb * 2;
    uint2 a0 = *(const uint2*)(su + OFF_S + (rA0    )*RSTR + kp);
    uint2 a1 = *(const uint2*)(su + OFF_S + (rA0 + 8)*RSTR + kp);
    const uint2* bptr = wtp + (size_t)ks*16*32;
    #pragma unroll
    for (int nt = 0; nt < 8; nt++){
      uint2 b = __ldg(bptr + nt*32);
      mma8(acc[nt], a0.x, a1.x, a0.y, a1.y, b.x, b.y);
    }
  }

  uint32_t ra[3][4];
  #pragma unroll
  for (int ks = 0; ks < 3; ks++){
    const int k = ks * 8 + kb;
    ra[ks][0] = su[OFF_RBF + rA0*20 + k];
    ra[ks][1] = su[OFF_RBF + (rA0+8)*20 + k];
    if (ks < 2){
      ra[ks][2] = su[OFF_RBF + rA0*20 + k + 4];
      ra[ks][3] = su[OFF_RBF + (rA0+8)*20 + k + 4];
    } else {
      ra[ks][2] = 0u; ra[ks][3] = 0u;
    }
  }

  const uint2* wwp = wt_ww + ((size_t)c*3*16 + nq*8)*32 + lane;

  #pragma unroll
  for (int nt = 0; nt < 8; nt++){
    const int cc = nb + nt*8 + 2*kb;
    const float2 bp = *(const float2*)(bphi_g + c*F + cc);
    const float2 bw = *(const float2*)(bw_g   + c*F + cc);
    float w4[4] = {0.f, 0.f, 0.f, 0.f};
    #pragma unroll
    for (int ks = 0; ks < 3; ks++){
      uint2 wb = __ldg(wwp + ((size_t)ks*16 + nt)*32);
      mma8(w4, ra[ks][0], ra[ks][1], ra[ks][2], ra[ks][3], wb.x, wb.y);
    }
    acc[nt][0] = (w4[0] + bw.x) * (acc[nt][0] + bp.x);
    acc[nt][1] = (w4[1] + bw.y) * (acc[nt][1] + bp.y);
    acc[nt][2] = (w4[2] + bw.x) * (acc[nt][2] + bp.x);
    acc[nt][3] = (w4[3] + bw.y) * (acc[nt][3] + bp.y);
    if (STASH_S == 0){
      *(float2*)(smf + OFF_P + (rA0    )*RSTR + cc) = make_float2(acc[nt][0], acc[nt][1]);
      *(float2*)(smf + OFF_P + (rA0 + 8)*RSTR + cc) = make_float2(acc[nt][2], acc[nt][3]);
    }
  }
  if (STASH_S == 1){
    __syncthreads();   // all warps done reading the s tile -> safe to overwrite
    #pragma unroll
    for (int nt = 0; nt < 8; nt++){
      const int cc = nb + nt*8 + 2*kb;
      *(float2*)(smf + OFF_S + (rA0    )*RSTR + cc) = make_float2(acc[nt][0], acc[nt][1]);
      *(float2*)(smf + OFF_S + (rA0 + 8)*RSTR + cc) = make_float2(acc[nt][2], acc[nt][3]);
    }
  }
}

__global__ void __launch_bounds__(NTHREADS, 2)
fused_message_kernel(
    const float* __restrict__ s_g, const float* __restrict__ r_g,
    const float* __restrict__ v_g, const int*   __restrict__ idx_g,
    const float* __restrict__ bphi_g, const float* __restrict__ bw_g,
    float* __restrict__ out_v, float* __restrict__ out_s, int E)
{
  extern __shared__ float smf[];
  uint32_t* su = (uint32_t*)smf;
  const int tid  = threadIdx.x;
  const int wid  = tid >> 5;
  const int lane = tid & 31;
  const int eb   = blockIdx.x * TM;
  const int* idx_sm = (const int*)(smf + OFF_IDX);
  const int* eid_sm = (const int*)(smf + OFF_EID);

  // ---- prologue phase 0: g partials + perm lookup ----
  if (wid == 0){
    float gs = 0.f;
    #pragma unroll
    for (int j = 0; j < 16; j++) gs += g_part[lane + 32*j];
    #pragma unroll
    for (int o = 16; o > 0; o >>= 1) gs += __shfl_xor_sync(0xffffffffu, gs, o);
    if (lane == 0) smf[OFF_G] = rsqrtf(gs);
  }
  if (tid < TM){
    int p = eb + tid;
    ((int*)(smf + OFF_EID))[tid] = (p < E) ? g_perm[p] : -1;
  }
  __syncthreads();

  // ---- prologue phase 1: s gather-stage + rbf/rn/idx ----
  {
    const uint4* s4 = (const uint4*)s_g;
    #pragma unroll
    for (int it = 0; it < 4; it++){
      int i = it * NTHREADS + tid;      // 1024 8-k groups
      int m = i >> 4, j = i & 15;
      int e = eid_sm[m];
      uint4 A0 = make_uint4(0u,0u,0u,0u), A1 = make_uint4(0u,0u,0u,0u);
      if (e >= 0){
        A0 = s4[(size_t)e * 32 + 2*j];
        A1 = s4[(size_t)e * 32 + 2*j + 1];
      }
      uint4 t0, t1;
      t0.x = to_tf32(__uint_as_float(A0.x)); t0.y = to_tf32(__uint_as_float(A1.x));
      t0.z = to_tf32(__uint_as_float(A0.y)); t0.w = to_tf32(__uint_as_float(A1.y));
      t1.x = to_tf32(__uint_as_float(A0.z)); t1.y = to_tf32(__uint_as_float(A1.z));
      t1.z = to_tf32(__uint_as_float(A0.w)); t1.w = to_tf32(__uint_as_float(A1.w));
      *(uint4*)(su + OFF_S + m*RSTR + 8*j)     = t0;
      *(uint4*)(su + OFF_S + m*RSTR + 8*j + 4) = t1;
    }
  }
  if (tid < TM){
    int e = eid_sm[tid];
    float rxv = 0.f, ryv = 0.f, rzv = 0.f;
    int node = -1;
    if (e >= 0){
      rxv = r_g[3*e+0]; ryv = r_g[3*e+1]; rzv = r_g[3*e+2];
      node = idx_g[e];
    }
    ((int*)(smf + OFF_IDX))[tid] = node;
    float rn = sqrtf(fmaf(rxv,rxv, fmaf(ryv,ryv, rzv*rzv)));
    float invg = smf[OFF_G];
    smf[OFF_RN + tid*4+0] = rxv*invg;
    smf[OFF_RN + tid*4+1] = ryv*invg;
    smf[OFF_RN + tid*4+2] = rzv*invg;
    smf[OFF_RN + tid*4+3] = 0.f;
    if (e >= 0){
      float inv_rn = 1.f / rn;
      const float c0 = 0.62831853071795864769f;  // pi / R_CUT
      #pragma unroll
      for (int k = 0; k < NRBF; k++){
        float t  = sinf((float)(k+1) * c0 * rn) * inv_rn;
        float rb = (t <= 5.0f) ? 0.5f*(cosf(c0*t) + 1.f) : 0.f;
        su[OFF_RBF + tid*20 + k] = to_tf32(rb);
      }
    } else {
      #pragma unroll
      for (int k = 0; k < NRBF; k++) su[OFF_RBF + tid*20 + k] = 0u;
    }
  }
  __syncthreads();

  // ===== chunk c=1 -> P ; epilogue S (run-merged: rows sorted by node) =====
  run_chunk<0>(su, smf, tid, 1, bphi_g, bw_g);
  __syncthreads();
  {
    const int row0 = wid * 8;
    int cur = idx_sm[row0];
    float4 a = *(const float4*)(smf + OFF_P + row0*RSTR + lane*4);
    #pragma unroll
    for (int i = 1; i < 8; i++){
      const int row = row0 + i;
      const int nd  = idx_sm[row];
      float4 v4 = *(const float4*)(smf + OFF_P + row*RSTR + lane*4);
      if (nd == cur){
        a.x += v4.x; a.y += v4.y; a.z += v4.z; a.w += v4.w;
      } else {
        if (cur >= 0) red4(out_s + (size_t)cur*F + lane*4, a.x, a.y, a.z, a.w);
        cur = nd; a = v4;
      }
    }
    if (cur >= 0) red4(out_s + (size_t)cur*F + lane*4, a.x, a.y, a.z, a.w);
  }
  __syncthreads();   // P reads done -> P reusable

  // ===== chunk c=0 -> P (sv) ; chunk c=2 -> regs -> (sync) -> S region (sr) =====
  run_chunk<0>(su, smf, tid, 0, bphi_g, bw_g);
  run_chunk<1>(su, smf, tid, 2, bphi_g, bw_g);   // internal sync before overwriting s tile
  __syncthreads();   // sv (P) and sr (S) both visible

  // ===== epilogue V (run-merged): out_v += sum_run( sv*v + sr*rn ) =====
  {
    const int row0 = wid * 8;
    int cur = -1;
    float4 a0 = make_float4(0.f,0.f,0.f,0.f);
    float4 a1 = make_float4(0.f,0.f,0.f,0.f);
    float4 a2 = make_float4(0.f,0.f,0.f,0.f);
    #pragma unroll
    for (int i = 0; i < 8; i++){
      const int row = row0 + i;
      const int nd  = idx_sm[row];
      if (nd != cur){
        if (cur >= 0){
          float* op = out_v + (size_t)cur * 3*F + lane*4;
          red4(op,         a0.x, a0.y, a0.z, a0.w);
          red4(op + F,     a1.x, a1.y, a1.z, a1.w);
          red4(op + 2*F,   a2.x, a2.y, a2.z, a2.w);
        }
        cur = nd;
        a0 = make_float4(0.f,0.f,0.f,0.f);
        a1 = make_float4(0.f,0.f,0.f,0.f);
        a2 = make_float4(0.f,0.f,0.f,0.f);
      }
      if (nd >= 0){
        const int e = eid_sm[row];
        float4 sv4 = *(const float4*)(smf + OFF_P + row*RSTR + lane*4);
        float4 sr4 = *(const float4*)(smf + OFF_S + row*RSTR + lane*4);
        const float* vp = v_g + (size_t)e * 3*F + lane*4;
        const float r0 = smf[OFF_RN + row*4 + 0];
        const float r1 = smf[OFF_RN + row*4 + 1];
        const float r2 = smf[OFF_RN + row*4 + 2];
        float4 vv;
        vv = *(const float4*)(vp);
        a0.x += fmaf(sv4.x, vv.x, sr4.x*r0); a0.y += fmaf(sv4.y, vv.y, sr4.y*r0);
        a0.z += fmaf(sv4.z, vv.z, sr4.z*r0); a0.w += fmaf(sv4.w, vv.w, sr4.w*r0);
        vv = *(const float4*)(vp + F);
        a1.x += fmaf(sv4.x, vv.x, sr4.x*r1); a1.y += fmaf(sv4.y, vv.y, sr4.y*r1);
        a1.z += fmaf(sv4.z, vv.z, sr4.z*r1); a1.w += fmaf(sv4.w, vv.w, sr4.w*r1);
        vv = *(const float4*)(vp + 2*F);
        a2.x += fmaf(sv4.x, vv.x, sr4.x*r2); a2.y += fmaf(sv4.y, vv.y, sr4.y*r2);
        a2.z += fmaf(sv4.z, vv.z, sr4.z*r2); a2.w += fmaf(sv4.w, vv.w, sr4.w*r2);
      }
    }
    if (cur >= 0){
      float* op = out_v + (size_t)cur * 3*F + lane*4;
      red4(op,       a0.x, a0.y, a0.z, a0.w);
      red4(op + F,   a1.x, a1.y, a1.z, a1.w);
      red4(op + 2*F, a2.x, a2.y, a2.z, a2.w);
    }
  }
}

extern "C" void kernel_launch(void* const* d_in, const int* in_sizes, int n_in,
                              void* d_out, int out_size){
  const float* s_g  = (const float*)d_in[0];
  const float* r_g  = (const float*)d_in[1];
  const float* v_g  = (const float*)d_in[2];
  const int*   idx  = (const int*)  d_in[3];
  const float* Wp   = (const float*)d_in[4];
  const float* bphi = (const float*)d_in[5];
  const float* Ww   = (const float*)d_in[6];
  const float* bw   = (const float*)d_in[7];
  const int E = in_sizes[1] / 3;            // r is (E,3)
  const int N = out_size / (4*F);           // out = out_v (N*3*F) ++ out_s (N*F)
  float* out_v = (float*)d_out;
  float* out_s = out_v + (size_t)N*3*F;

  zero_kernel<<<512, 256>>>((float4*)d_out, out_size/4, N);
  prep_w_kernel<<<512, 256>>>(Wp, Ww, r_g, 3*E);
  hist_kernel<<<512, 256>>>(idx, E);
  scan_kernel<<<1, 256>>>(N);
  scatter_kernel<<<512, 256>>>(idx, E);
  cudaFuncSetAttribute(fused_message_kernel,
                       cudaFuncAttributeMaxDynamicSharedMemorySize, SMEM_BYTES);
  const int blocks = (E + TM - 1) / TM;
  fused_message_kernel<<<blocks, NTHREADS, SMEM_BYTES>>>(
      s_g, r_g, v_g, idx, bphi, bw, out_v, out_s, E);
}

// round 16
// speedup vs baseline: 1.0061x; 1.0061x over previous
#include <cuda_runtime.h>
#include <cstdint>

#define F        128
#define TM       64
#define NTHREADS 256
#define NRBF     20
#define RSTR     136   // row stride (floats): == 8 mod 32 -> conflict-free fragment STS/LDS
#define MAXE     524288
#define MAXN     16384

// smem offsets in FLOATS
#define OFF_S    0            // s tile [64][136]; later reused as sr stash   8704
#define OFF_P    8704         // stash buf [64][136]                          8704
#define OFF_RBF  17408        // rbf [64][20]                                 1280
#define OFF_IDX  18688        // 64 ints (node per row, -1 invalid)
#define OFF_EID  18752        // 64 ints (edge id per row, -1 invalid)
#define OFF_RN   18816        // 64*4 floats
#define OFF_G    19072        // 1 float
#define SMEM_FLOATS 19076
#define SMEM_BYTES  (SMEM_FLOATS * 4)

__device__ float g_part[512];
__device__ int   g_cnt[MAXN];
__device__ int   g_off[MAXN];
__device__ int   g_perm[MAXE];
// fragment-major packed weights (built once per launch)
//   wt_phi[((c*16 + ks)*16 + ntile)*32 + lane] = {W[k][c*128+n], W[k+4][c*128+n]}
__device__ uint2 wt_phi[3 * 16 * 16 * 32];
__device__ uint2 wt_ww [3 * 3 * 16 * 32];

static __device__ __forceinline__ uint32_t to_tf32(float x){
  uint32_t t;
  asm("cvt.rna.tf32.f32 %0, %1;" : "=r"(t) : "f"(x));
  return t;
}
static __device__ __forceinline__ void mma8(float c[4], uint32_t a0, uint32_t a1,
    uint32_t a2, uint32_t a3, uint32_t b0, uint32_t b1){
  asm volatile("mma.sync.aligned.m16n8k8.row.col.f32.tf32.tf32.f32 "
    "{%0,%1,%2,%3}, {%4,%5,%6,%7}, {%8,%9}, {%0,%1,%2,%3};"
    : "+f"(c[0]), "+f"(c[1]), "+f"(c[2]), "+f"(c[3])
    : "r"(a0), "r"(a1), "r"(a2), "r"(a3), "r"(b0), "r"(b1));
}
static __device__ __forceinline__ void red4(float* p, float a, float b, float c, float d){
  asm volatile("red.global.add.v4.f32 [%0], {%1, %2, %3, %4};"
               :: "l"(p), "f"(a), "f"(b), "f"(c), "f"(d) : "memory");
}

// ---- launch 1: zero output + node counters ----
__global__ void zero_kernel(float4* __restrict__ out4, int nout4, int N){
  const int gtid = blockIdx.x * blockDim.x + threadIdx.x;
  const int gstr = gridDim.x * blockDim.x;
  for (int i = gtid; i < nout4; i += gstr)
    out4[i] = make_float4(0.f, 0.f, 0.f, 0.f);
  for (int i = gtid; i < N; i += gstr)
    g_cnt[i] = 0;
}

// ---- launch 2: pack weights + frobenius partials + node histogram ----
__global__ void prep_hist_kernel(const float* __restrict__ Wp_g,
                                 const float* __restrict__ Ww_g,
                                 const float* __restrict__ r, int n,
                                 const int* __restrict__ idx_g, int E){
  const int gtid = blockIdx.x * blockDim.x + threadIdx.x;
  const int gstr = gridDim.x * blockDim.x;
  for (int i = gtid; i < 3*16*16*32; i += gstr){
    int l = i & 31, t = (i >> 5) & 15, ks = (i >> 9) & 15, c = i >> 13;
    int qr = l >> 2, kb = l & 3;
    int nn = t*8 + qr, k = ks*8 + kb;
    uint2 val;
    val.x = to_tf32(Wp_g[(size_t)k    *384 + c*128 + nn]);
    val.y = to_tf32(Wp_g[(size_t)(k+4)*384 + c*128 + nn]);
    wt_phi[i] = val;
  }
  for (int i = gtid; i < 3*3*16*32; i += gstr){
    int l = i & 31, t = (i >> 5) & 15, rr = i >> 9;   // rr = c*3 + ks
    int ks = rr % 3, c = rr / 3;
    int qr = l >> 2, kb = l & 3;
    int nn = t*8 + qr, k = ks*8 + kb;
    uint2 val;
    val.x = to_tf32(Ww_g[(size_t)k*384 + c*128 + nn]);
    val.y = (k + 4 < NRBF) ? to_tf32(Ww_g[(size_t)(k+4)*384 + c*128 + nn]) : 0u;
    wt_ww[i] = val;
  }
  // histogram
  for (int e = gtid; e < E; e += gstr)
    atomicAdd(&g_cnt[idx_g[e]], 1);
  // frobenius sum of squares
  float s = 0.f;
  for (int i = gtid; i < n; i += gstr){
    float x = r[i];
    s = fmaf(x, x, s);
  }
  #pragma unroll
  for (int o = 16; o > 0; o >>= 1) s += __shfl_xor_sync(0xffffffffu, s, o);
  __shared__ float ws[8];
  int lane = threadIdx.x & 31, w = threadIdx.x >> 5;
  if (lane == 0) ws[w] = s;
  __syncthreads();
  if (threadIdx.x < 32){
    s = (threadIdx.x < 8) ? ws[threadIdx.x] : 0.f;
    #pragma unroll
    for (int o = 4; o > 0; o >>= 1) s += __shfl_xor_sync(0xffffffffu, s, o);
    if (threadIdx.x == 0) g_part[blockIdx.x] = s;
  }
}

// ---- launch 3: exclusive scan (single block, 1024 threads) ----
__global__ void scan_kernel(int N){
  const int tid  = threadIdx.x;
  const int lane = tid & 31, w = tid >> 5;
  const int chunk = (N + 1023) >> 10;
  const int s0 = min(tid * chunk, N), e0 = min(s0 + chunk, N);
  int sum = 0;
  for (int i = s0; i < e0; i++) sum += g_cnt[i];
  // warp inclusive scan
  int x = sum;
  #pragma unroll
  for (int o = 1; o < 32; o <<= 1){
    int y = __shfl_up_sync(0xffffffffu, x, o);
    if (lane >= o) x += y;
  }
  __shared__ int wsum[32];
  if (lane == 31) wsum[w] = x;
  __syncthreads();
  if (w == 0){
    int y = wsum[lane];
    #pragma unroll
    for (int o = 1; o < 32; o <<= 1){
      int z = __shfl_up_sync(0xffffffffu, y, o);
      if (lane >= o) y += z;
    }
    wsum[lane] = y;   // inclusive warp-sums prefix
  }
  __syncthreads();
  int base = (w > 0) ? wsum[w-1] : 0;
  int off = base + x - sum;     // exclusive prefix for this thread's chunk
  for (int i = s0; i < e0; i++){
    int c = g_cnt[i];
    g_off[i] = off;             // fill cursor
    off += c;
  }
}

// ---- launch 4: scatter edges into node-sorted order ----
__global__ void scatter_kernel(const int* __restrict__ idx_g, int E){
  const int gtid = blockIdx.x * blockDim.x + threadIdx.x;
  const int gstr = gridDim.x * blockDim.x;
  for (int e = gtid; e < E; e += gstr){
    int pos = atomicAdd(&g_off[idx_g[e]], 1);
    g_perm[pos] = e;
  }
}

// compute chunk c, gate.
// STASH_S == 0: stash gated output inline into OFF_P.
// STASH_S == 1: hold gated output in regs, __syncthreads (s tile dead), stash into OFF_S.
template<int STASH_S>
static __device__ __forceinline__ void run_chunk(
    const uint32_t* __restrict__ su, float* __restrict__ smf,
    int tid, int c,
    const float* __restrict__ bphi_g, const float* __restrict__ bw_g)
{
  const int wid  = tid >> 5;
  const int lane = tid & 31;
  const int mg   = wid >> 1;
  const int nq   = wid & 1;
  const int qr   = lane >> 2;
  const int kb   = lane & 3;
  const int rA0  = mg * 16 + qr;
  const int nb   = nq * 64;

  float acc[8][4];
  #pragma unroll
  for (int nt = 0; nt < 8; nt++){
    acc[nt][0]=0.f; acc[nt][1]=0.f; acc[nt][2]=0.f; acc[nt][3]=0.f;
  }

  const uint2* wtp = wt_phi + ((size_t)c*16*16 + nq*8)*32 + lane;
  #pragma unroll 4
  for (int ks = 0; ks < 16; ks++){
    const int kp = ks * 8 + kb * 2;
    uint2 a0 = *(const uint2*)(su + OFF_S + (rA0    )*RSTR + kp);
    uint2 a1 = *(const uint2*)(su + OFF_S + (rA0 + 8)*RSTR + kp);
    const uint2* bptr = wtp + (size_t)ks*16*32;
    #pragma unroll
    for (int nt = 0; nt < 8; nt++){
      uint2 b = __ldg(bptr + nt*32);
      mma8(acc[nt], a0.x, a1.x, a0.y, a1.y, b.x, b.y);
    }
  }

  uint32_t ra[3][4];
  #pragma unroll
  for (int ks = 0; ks < 3; ks++){
    const int k = ks * 8 + kb;
    ra[ks][0] = su[OFF_RBF + rA0*20 + k];
    ra[ks][1] = su[OFF_RBF + (rA0+8)*20 + k];
    if (ks < 2){
      ra[ks][2] = su[OFF_RBF + rA0*20 + k + 4];
      ra[ks][3] = su[OFF_RBF + (rA0+8)*20 + k + 4];
    } else {
      ra[ks][2] = 0u; ra[ks][3] = 0u;
    }
  }

  const uint2* wwp = wt_ww + ((size_t)c*3*16 + nq*8)*32 + lane;

  #pragma unroll
  for (int nt = 0; nt < 8; nt++){
    const int cc = nb + nt*8 + 2*kb;
    const float2 bp = *(const float2*)(bphi_g + c*F + cc);
    const float2 bw = *(const float2*)(bw_g   + c*F + cc);
    float w4[4] = {0.f, 0.f, 0.f, 0.f};
    #pragma unroll
    for (int ks = 0; ks < 3; ks++){
      uint2 wb = __ldg(wwp + ((size_t)ks*16 + nt)*32);
      mma8(w4, ra[ks][0], ra[ks][1], ra[ks][2], ra[ks][3], wb.x, wb.y);
    }
    acc[nt][0] = (w4[0] + bw.x) * (acc[nt][0] + bp.x);
    acc[nt][1] = (w4[1] + bw.y) * (acc[nt][1] + bp.y);
    acc[nt][2] = (w4[2] + bw.x) * (acc[nt][2] + bp.x);
    acc[nt][3] = (w4[3] + bw.y) * (acc[nt][3] + bp.y);
    if (STASH_S == 0){
      *(float2*)(smf + OFF_P + (rA0    )*RSTR + cc) = make_float2(acc[nt][0], acc[nt][1]);
      *(float2*)(smf + OFF_P + (rA0 + 8)*RSTR + cc) = make_float2(acc[nt][2], acc[nt][3]);
    }
  }
  if (STASH_S == 1){
    __syncthreads();   // all warps done reading the s tile -> safe to overwrite
    #pragma unroll
    for (int nt = 0; nt < 8; nt++){
      const int cc = nb + nt*8 + 2*kb;
      *(float2*)(smf + OFF_S + (rA0    )*RSTR + cc) = make_float2(acc[nt][0], acc[nt][1]);
      *(float2*)(smf + OFF_S + (rA0 + 8)*RSTR + cc) = make_float2(acc[nt][2], acc[nt][3]);
    }
  }
}

__global__ void __launch_bounds__(NTHREADS, 2)
fused_message_kernel(
    const float* __restrict__ s_g, const float* __restrict__ r_g,
    const float* __restrict__ v_g, const int*   __restrict__ idx_g,
    const float* __restrict__ bphi_g, const float* __restrict__ bw_g,
    float* __restrict__ out_v, float* __restrict__ out_s, int E)
{
  extern __shared__ float smf[];
  uint32_t* su = (uint32_t*)smf;
  const int tid  = threadIdx.x;
  const int wid  = tid >> 5;
  const int lane = tid & 31;
  const int eb   = blockIdx.x * TM;
  const int* idx_sm = (const int*)(smf + OFF_IDX);
  const int* eid_sm = (const int*)(smf + OFF_EID);

  // ---- prologue phase 0: g partials + perm lookup ----
  if (wid == 0){
    float gs = 0.f;
    #pragma unroll
    for (int j = 0; j < 16; j++) gs += g_part[lane + 32*j];
    #pragma unroll
    for (int o = 16; o > 0; o >>= 1) gs += __shfl_xor_sync(0xffffffffu, gs, o);
    if (lane == 0) smf[OFF_G] = rsqrtf(gs);
  }
  if (tid < TM){
    int p = eb + tid;
    ((int*)(smf + OFF_EID))[tid] = (p < E) ? g_perm[p] : -1;
  }
  __syncthreads();

  // ---- prologue phase 1: s gather-stage + rbf/rn/idx ----
  {
    const uint4* s4 = (const uint4*)s_g;
    #pragma unroll
    for (int it = 0; it < 4; it++){
      int i = it * NTHREADS + tid;      // 1024 8-k groups
      int m = i >> 4, j = i & 15;
      int e = eid_sm[m];
      uint4 A0 = make_uint4(0u,0u,0u,0u), A1 = make_uint4(0u,0u,0u,0u);
      if (e >= 0){
        A0 = s4[(size_t)e * 32 + 2*j];
        A1 = s4[(size_t)e * 32 + 2*j + 1];
      }
      uint4 t0, t1;
      t0.x = to_tf32(__uint_as_float(A0.x)); t0.y = to_tf32(__uint_as_float(A1.x));
      t0.z = to_tf32(__uint_as_float(A0.y)); t0.w = to_tf32(__uint_as_float(A1.y));
      t1.x = to_tf32(__uint_as_float(A0.z)); t1.y = to_tf32(__uint_as_float(A1.z));
      t1.z = to_tf32(__uint_as_float(A0.w)); t1.w = to_tf32(__uint_as_float(A1.w));
      *(uint4*)(su + OFF_S + m*RSTR + 8*j)     = t0;
      *(uint4*)(su + OFF_S + m*RSTR + 8*j + 4) = t1;
    }
  }
  if (tid < TM){
    int e = eid_sm[tid];
    float rxv = 0.f, ryv = 0.f, rzv = 0.f;
    int node = -1;
    if (e >= 0){
      rxv = r_g[3*e+0]; ryv = r_g[3*e+1]; rzv = r_g[3*e+2];
      node = idx_g[e];
    }
    ((int*)(smf + OFF_IDX))[tid] = node;
    float rn = sqrtf(fmaf(rxv,rxv, fmaf(ryv,ryv, rzv*rzv)));
    float invg = smf[OFF_G];
    smf[OFF_RN + tid*4+0] = rxv*invg;
    smf[OFF_RN + tid*4+1] = ryv*invg;
    smf[OFF_RN + tid*4+2] = rzv*invg;
    smf[OFF_RN + tid*4+3] = 0.f;
    if (e >= 0){
      float inv_rn = 1.f / rn;
      const float c0 = 0.62831853071795864769f;  // pi / R_CUT
      #pragma unroll
      for (int k = 0; k < NRBF; k++){
        float t  = sinf((float)(k+1) * c0 * rn) * inv_rn;
        float rb = (t <= 5.0f) ? 0.5f*(cosf(c0*t) + 1.f) : 0.f;
        su[OFF_RBF + tid*20 + k] = to_tf32(rb);
      }
    } else {
      #pragma unroll
      for (int k = 0; k < NRBF; k++) su[OFF_RBF + tid*20 + k] = 0u;
    }
  }
  __syncthreads();

  // ===== chunk c=1 -> P ; epilogue S (run-merged: rows sorted by node) =====
  run_chunk<0>(su, smf, tid, 1, bphi_g, bw_g);
  __syncthreads();
  {
    const int row0 = wid * 8;
    int cur = idx_sm[row0];
    float4 a = *(const float4*)(smf + OFF_P + row0*RSTR + lane*4);
    #pragma unroll
    for (int i = 1; i < 8; i++){
      const int row = row0 + i;
      const int nd  = idx_sm[row];
      float4 v4 = *(const float4*)(smf + OFF_P + row*RSTR + lane*4);
      if (nd == cur){
        a.x += v4.x; a.y += v4.y; a.z += v4.z; a.w += v4.w;
      } else {
        if (cur >= 0) red4(out_s + (size_t)cur*F + lane*4, a.x, a.y, a.z, a.w);
        cur = nd; a = v4;
      }
    }
    if (cur >= 0) red4(out_s + (size_t)cur*F + lane*4, a.x, a.y, a.z, a.w);
  }
  __syncthreads();   // P reads done -> P reusable

  // ===== chunk c=0 -> P (sv) ; chunk c=2 -> regs -> (sync) -> S region (sr) =====
  run_chunk<0>(su, smf, tid, 0, bphi_g, bw_g);
  run_chunk<1>(su, smf, tid, 2, bphi_g, bw_g);   // internal sync before overwriting s tile
  __syncthreads();   // sv (P) and sr (S) both visible

  // ===== epilogue V (run-merged): out_v += sum_run( sv*v + sr*rn ) =====
  {
    const int row0 = wid * 8;
    int cur = -1;
    float4 a0 = make_float4(0.f,0.f,0.f,0.f);
    float4 a1 = make_float4(0.f,0.f,0.f,0.f);
    float4 a2 = make_float4(0.f,0.f,0.f,0.f);
    #pragma unroll
    for (int i = 0; i < 8; i++){
      const int row = row0 + i;
      const int nd  = idx_sm[row];
      if (nd != cur){
        if (cur >= 0){
          float* op = out_v + (size_t)cur * 3*F + lane*4;
          red4(op,         a0.x, a0.y, a0.z, a0.w);
          red4(op + F,     a1.x, a1.y, a1.z, a1.w);
          red4(op + 2*F,   a2.x, a2.y, a2.z, a2.w);
        }
        cur = nd;
        a0 = make_float4(0.f,0.f,0.f,0.f);
        a1 = make_float4(0.f,0.f,0.f,0.f);
        a2 = make_float4(0.f,0.f,0.f,0.f);
      }
      if (nd >= 0){
        const int e = eid_sm[row];
        float4 sv4 = *(const float4*)(smf + OFF_P + row*RSTR + lane*4);
        float4 sr4 = *(const float4*)(smf + OFF_S + row*RSTR + lane*4);
        const float* vp = v_g + (size_t)e * 3*F + lane*4;
        const float r0 = smf[OFF_RN + row*4 + 0];
        const float r1 = smf[OFF_RN + row*4 + 1];
        const float r2 = smf[OFF_RN + row*4 + 2];
        float4 vv;
        vv = *(const float4*)(vp);
        a0.x += fmaf(sv4.x, vv.x, sr4.x*r0); a0.y += fmaf(sv4.y, vv.y, sr4.y*r0);
        a0.z += fmaf(sv4.z, vv.z, sr4.z*r0); a0.w += fmaf(sv4.w, vv.w, sr4.w*r0);
        vv = *(const float4*)(vp + F);
        a1.x += fmaf(sv4.x, vv.x, sr4.x*r1); a1.y += fmaf(sv4.y, vv.y, sr4.y*r1);
        a1.z += fmaf(sv4.z, vv.z, sr4.z*r1); a1.w += fmaf(sv4.w, vv.w, sr4.w*r1);
        vv = *(const float4*)(vp + 2*F);
        a2.x += fmaf(sv4.x, vv.x, sr4.x*r2); a2.y += fmaf(sv4.y, vv.y, sr4.y*r2);
        a2.z += fmaf(sv4.z, vv.z, sr4.z*r2); a2.w += fmaf(sv4.w, vv.w, sr4.w*r2);
      }
    }
    if (cur >= 0){
      float* op = out_v + (size_t)cur * 3*F + lane*4;
      red4(op,       a0.x, a0.y, a0.z, a0.w);
      red4(op + F,   a1.x, a1.y, a1.z, a1.w);
      red4(op + 2*F, a2.x, a2.y, a2.z, a2.w);
    }
  }
}

extern "C" void kernel_launch(void* const* d_in, const int* in_sizes, int n_in,
                              void* d_out, int out_size){
  const float* s_g  = (const float*)d_in[0];
  const float* r_g  = (const float*)d_in[1];
  const float* v_g  = (const float*)d_in[2];
  const int*   idx  = (const int*)  d_in[3];
  const float* Wp   = (const float*)d_in[4];
  const float* bphi = (const float*)d_in[5];
  const float* Ww   = (const float*)d_in[6];
  const float* bw   = (const float*)d_in[7];
  const int E = in_sizes[1] / 3;            // r is (E,3)
  const int N = out_size / (4*F);           // out = out_v (N*3*F) ++ out_s (N*F)
  float* out_v = (float*)d_out;
  float* out_s = out_v + (size_t)N*3*F;

  zero_kernel<<<512, 256>>>((float4*)d_out, out_size/4, N);
  prep_hist_kernel<<<512, 256>>>(Wp, Ww, r_g, 3*E, idx, E);
  scan_kernel<<<1, 1024>>>(N);
  scatter_kernel<<<512, 256>>>(idx, E);
  cudaFuncSetAttribute(fused_message_kernel,
                       cudaFuncAttributeMaxDynamicSharedMemorySize, SMEM_BYTES);
  const int blocks = (E + TM - 1) / TM;
  fused_message_kernel<<<blocks, NTHREADS, SMEM_BYTES>>>(
      s_g, r_g, v_g, idx, bphi, bw, out_v, out_s, E);
}

// round 17
// speedup vs baseline: 1.0469x; 1.0405x over previous
#include <cuda_runtime.h>
#include <cstdint>

#define F        128
#define TM       64
#define NTHREADS 256
#define NRBF     20
#define RSTR     136   // row stride (floats): == 8 mod 32 -> conflict-free fragment STS/LDS
#define MAXE     524288
#define MAXN     16384

// smem offsets in FLOATS
#define OFF_S    0            // s tile [64][136]; later reused as sr stash   8704
#define OFF_P    8704         // stash buf [64][136]                          8704
#define OFF_RBF  17408        // rbf [64][20]                                 1280
#define OFF_IDX  18688        // 64 ints (node per row, -1 invalid)
#define OFF_EID  18752        // 64 ints (edge id per row, -1 invalid)
#define OFF_RN   18816        // 64*4 floats
#define OFF_G    19072        // 1 float
#define SMEM_FLOATS 19076
#define SMEM_BYTES  (SMEM_FLOATS * 4)

__device__ float g_part[512];
__device__ int   g_cnt[MAXN];     // zero at module load; re-zeroed by scatter_kernel each call
__device__ int   g_off[MAXN];
__device__ int   g_perm[MAXE];
// fragment-major packed weights (built once per launch)
//   wt_phi[((c*16 + ks)*16 + ntile)*32 + lane] = {W[k][c*128+n], W[k+4][c*128+n]}
__device__ uint2 wt_phi[3 * 16 * 16 * 32];
__device__ uint2 wt_ww [3 * 3 * 16 * 32];

static __device__ __forceinline__ uint32_t to_tf32(float x){
  uint32_t t;
  asm("cvt.rna.tf32.f32 %0, %1;" : "=r"(t) : "f"(x));
  return t;
}
static __device__ __forceinline__ void mma8(float c[4], uint32_t a0, uint32_t a1,
    uint32_t a2, uint32_t a3, uint32_t b0, uint32_t b1){
  asm volatile("mma.sync.aligned.m16n8k8.row.col.f32.tf32.tf32.f32 "
    "{%0,%1,%2,%3}, {%4,%5,%6,%7}, {%8,%9}, {%0,%1,%2,%3};"
    : "+f"(c[0]), "+f"(c[1]), "+f"(c[2]), "+f"(c[3])
    : "r"(a0), "r"(a1), "r"(a2), "r"(a3), "r"(b0), "r"(b1));
}
static __device__ __forceinline__ void red4(float* p, float a, float b, float c, float d){
  asm volatile("red.global.add.v4.f32 [%0], {%1, %2, %3, %4};"
               :: "l"(p), "f"(a), "f"(b), "f"(c), "f"(d) : "memory");
}

// ---- launch 1: pack weights + frobenius partials + node histogram + zero output ----
__global__ void prep_hist_kernel(const float* __restrict__ Wp_g,
                                 const float* __restrict__ Ww_g,
                                 const float* __restrict__ r, int n,
                                 const int* __restrict__ idx_g, int E,
                                 float4* __restrict__ out4, int nout4){
  const int gtid = blockIdx.x * blockDim.x + threadIdx.x;
  const int gstr = gridDim.x * blockDim.x;
  for (int i = gtid; i < nout4; i += gstr)
    out4[i] = make_float4(0.f, 0.f, 0.f, 0.f);
  for (int i = gtid; i < 3*16*16*32; i += gstr){
    int l = i & 31, t = (i >> 5) & 15, ks = (i >> 9) & 15, c = i >> 13;
    int qr = l >> 2, kb = l & 3;
    int nn = t*8 + qr, k = ks*8 + kb;
    uint2 val;
    val.x = to_tf32(Wp_g[(size_t)k    *384 + c*128 + nn]);
    val.y = to_tf32(Wp_g[(size_t)(k+4)*384 + c*128 + nn]);
    wt_phi[i] = val;
  }
  for (int i = gtid; i < 3*3*16*32; i += gstr){
    int l = i & 31, t = (i >> 5) & 15, rr = i >> 9;   // rr = c*3 + ks
    int ks = rr % 3, c = rr / 3;
    int qr = l >> 2, kb = l & 3;
    int nn = t*8 + qr, k = ks*8 + kb;
    uint2 val;
    val.x = to_tf32(Ww_g[(size_t)k*384 + c*128 + nn]);
    val.y = (k + 4 < NRBF) ? to_tf32(Ww_g[(size_t)(k+4)*384 + c*128 + nn]) : 0u;
    wt_ww[i] = val;
  }
  // histogram (g_cnt zeroed by previous scatter_kernel / module init)
  for (int e = gtid; e < E; e += gstr)
    atomicAdd(&g_cnt[idx_g[e]], 1);
  // frobenius sum of squares
  float s = 0.f;
  for (int i = gtid; i < n; i += gstr){
    float x = r[i];
    s = fmaf(x, x, s);
  }
  #pragma unroll
  for (int o = 16; o > 0; o >>= 1) s += __shfl_xor_sync(0xffffffffu, s, o);
  __shared__ float ws[8];
  int lane = threadIdx.x & 31, w = threadIdx.x >> 5;
  if (lane == 0) ws[w] = s;
  __syncthreads();
  if (threadIdx.x < 32){
    s = (threadIdx.x < 8) ? ws[threadIdx.x] : 0.f;
    #pragma unroll
    for (int o = 4; o > 0; o >>= 1) s += __shfl_xor_sync(0xffffffffu, s, o);
    if (threadIdx.x == 0) g_part[blockIdx.x] = s;
  }
}

// ---- launch 2: exclusive scan (single block, 1024 threads) ----
__global__ void scan_kernel(int N){
  const int tid  = threadIdx.x;
  const int lane = tid & 31, w = tid >> 5;
  const int chunk = (N + 1023) >> 10;
  const int s0 = min(tid * chunk, N), e0 = min(s0 + chunk, N);
  int sum = 0;
  for (int i = s0; i < e0; i++) sum += g_cnt[i];
  int x = sum;
  #pragma unroll
  for (int o = 1; o < 32; o <<= 1){
    int y = __shfl_up_sync(0xffffffffu, x, o);
    if (lane >= o) x += y;
  }
  __shared__ int wsum[32];
  if (lane == 31) wsum[w] = x;
  __syncthreads();
  if (w == 0){
    int y = wsum[lane];
    #pragma unroll
    for (int o = 1; o < 32; o <<= 1){
      int z = __shfl_up_sync(0xffffffffu, y, o);
      if (lane >= o) y += z;
    }
    wsum[lane] = y;
  }
  __syncthreads();
  int base = (w > 0) ? wsum[w-1] : 0;
  int off = base + x - sum;
  for (int i = s0; i < e0; i++){
    int c = g_cnt[i];
    g_off[i] = off;
    off += c;
  }
}

// ---- launch 3: scatter edges into node-sorted order + re-zero cnt for next call ----
__global__ void scatter_kernel(const int* __restrict__ idx_g, int E, int N){
  const int gtid = blockIdx.x * blockDim.x + threadIdx.x;
  const int gstr = gridDim.x * blockDim.x;
  for (int e = gtid; e < E; e += gstr){
    int pos = atomicAdd(&g_off[idx_g[e]], 1);
    g_perm[pos] = e;
  }
  for (int i = gtid; i < N; i += gstr)
    g_cnt[i] = 0;
}

// compute chunk c, gate. Warp tile 32m x 32n (B fragments feed 2 m-tiles).
// STASH_S == 0: stash gated output inline into OFF_P.
// STASH_S == 1: hold gated output in regs, __syncthreads (s tile dead), stash into OFF_S.
template<int STASH_S>
static __device__ __forceinline__ void run_chunk(
    const uint32_t* __restrict__ su, float* __restrict__ smf,
    int tid, int c,
    const float* __restrict__ bphi_g, const float* __restrict__ bw_g)
{
  const int wid  = tid >> 5;
  const int lane = tid & 31;
  const int mg   = wid >> 2;          // m-group: 32 edges
  const int nq   = wid & 3;           // n quarter (32 cols)
  const int qr   = lane >> 2;
  const int kb   = lane & 3;
  const int rA0  = mg * 32 + qr;
  const int nb   = nq * 32;

  float acc[2][4][4];
  #pragma unroll
  for (int mt = 0; mt < 2; mt++)
    #pragma unroll
    for (int nt = 0; nt < 4; nt++){
      acc[mt][nt][0]=0.f; acc[mt][nt][1]=0.f; acc[mt][nt][2]=0.f; acc[mt][nt][3]=0.f;
    }

  // ---- phi = s @ Wphi(c) : 32m x 32n warp tile; B fragments feed 2 m-tiles ----
  const uint2* wtp = wt_phi + ((size_t)c*16*16 + nq*4)*32 + lane;
  #pragma unroll 4
  for (int ks = 0; ks < 16; ks++){
    const int kp = ks * 8 + kb * 2;
    uint2 a00 = *(const uint2*)(su + OFF_S + (rA0     )*RSTR + kp);
    uint2 a01 = *(const uint2*)(su + OFF_S + (rA0 +  8)*RSTR + kp);
    uint2 a10 = *(const uint2*)(su + OFF_S + (rA0 + 16)*RSTR + kp);
    uint2 a11 = *(const uint2*)(su + OFF_S + (rA0 + 24)*RSTR + kp);
    const uint2* bptr = wtp + (size_t)ks*16*32;
    #pragma unroll
    for (int nt = 0; nt < 4; nt++){
      uint2 b = __ldg(bptr + nt*32);
      mma8(acc[0][nt], a00.x, a01.x, a00.y, a01.y, b.x, b.y);
      mma8(acc[1][nt], a10.x, a11.x, a10.y, a11.y, b.x, b.y);
    }
  }

  // ---- rbf fragments (K = 20) for both m-tiles ----
  uint32_t ra[2][3][4];
  #pragma unroll
  for (int mt = 0; mt < 2; mt++){
    const int rm = rA0 + mt*16;
    #pragma unroll
    for (int ks = 0; ks < 3; ks++){
      const int k = ks * 8 + kb;
      ra[mt][ks][0] = su[OFF_RBF + rm*20 + k];
      ra[mt][ks][1] = su[OFF_RBF + (rm+8)*20 + k];
      if (ks < 2){
        ra[mt][ks][2] = su[OFF_RBF + rm*20 + k + 4];
        ra[mt][ks][3] = su[OFF_RBF + (rm+8)*20 + k + 4];
      } else {
        ra[mt][ks][2] = 0u; ra[mt][ks][3] = 0u;
      }
    }
  }

  const uint2* wwp = wt_ww + ((size_t)c*3*16 + nq*4)*32 + lane;

  #pragma unroll
  for (int nt = 0; nt < 4; nt++){
    const int cc = nb + nt*8 + 2*kb;
    const float2 bp = *(const float2*)(bphi_g + c*F + cc);
    const float2 bw = *(const float2*)(bw_g   + c*F + cc);
    uint2 wb[3];
    #pragma unroll
    for (int ks = 0; ks < 3; ks++)
      wb[ks] = __ldg(wwp + ((size_t)ks*16 + nt)*32);
    #pragma unroll
    for (int mt = 0; mt < 2; mt++){
      float w4[4] = {0.f, 0.f, 0.f, 0.f};
      #pragma unroll
      for (int ks = 0; ks < 3; ks++)
        mma8(w4, ra[mt][ks][0], ra[mt][ks][1], ra[mt][ks][2], ra[mt][ks][3],
             wb[ks].x, wb[ks].y);
      float* a = acc[mt][nt];
      a[0] = (w4[0] + bw.x) * (a[0] + bp.x);
      a[1] = (w4[1] + bw.y) * (a[1] + bp.y);
      a[2] = (w4[2] + bw.x) * (a[2] + bp.x);
      a[3] = (w4[3] + bw.y) * (a[3] + bp.y);
      if (STASH_S == 0){
        const int rm = rA0 + mt*16;
        *(float2*)(smf + OFF_P + (rm    )*RSTR + cc) = make_float2(a[0], a[1]);
        *(float2*)(smf + OFF_P + (rm + 8)*RSTR + cc) = make_float2(a[2], a[3]);
      }
    }
  }
  if (STASH_S == 1){
    __syncthreads();   // all warps done reading the s tile -> safe to overwrite
    #pragma unroll
    for (int mt = 0; mt < 2; mt++)
      #pragma unroll
      for (int nt = 0; nt < 4; nt++){
        const int cc = nb + nt*8 + 2*kb;
        const int rm = rA0 + mt*16;
        *(float2*)(smf + OFF_S + (rm    )*RSTR + cc) = make_float2(acc[mt][nt][0], acc[mt][nt][1]);
        *(float2*)(smf + OFF_S + (rm + 8)*RSTR + cc) = make_float2(acc[mt][nt][2], acc[mt][nt][3]);
      }
  }
}

__global__ void __launch_bounds__(NTHREADS, 2)
fused_message_kernel(
    const float* __restrict__ s_g, const float* __restrict__ r_g,
    const float* __restrict__ v_g, const int*   __restrict__ idx_g,
    const float* __restrict__ bphi_g, const float* __restrict__ bw_g,
    float* __restrict__ out_v, float* __restrict__ out_s, int E)
{
  extern __shared__ float smf[];
  uint32_t* su = (uint32_t*)smf;
  const int tid  = threadIdx.x;
  const int wid  = tid >> 5;
  const int lane = tid & 31;
  const int eb   = blockIdx.x * TM;
  const int* idx_sm = (const int*)(smf + OFF_IDX);
  const int* eid_sm = (const int*)(smf + OFF_EID);

  // ---- prologue phase 0: g partials + perm lookup ----
  if (wid == 0){
    float gs = 0.f;
    #pragma unroll
    for (int j = 0; j < 16; j++) gs += g_part[lane + 32*j];
    #pragma unroll
    for (int o = 16; o > 0; o >>= 1) gs += __shfl_xor_sync(0xffffffffu, gs, o);
    if (lane == 0) smf[OFF_G] = rsqrtf(gs);
  }
  if (tid < TM){
    int p = eb + tid;
    ((int*)(smf + OFF_EID))[tid] = (p < E) ? g_perm[p] : -1;
  }
  __syncthreads();

  // ---- prologue phase 1: s gather-stage + rbf/rn/idx ----
  {
    const uint4* s4 = (const uint4*)s_g;
    #pragma unroll
    for (int it = 0; it < 4; it++){
      int i = it * NTHREADS + tid;      // 1024 8-k groups
      int m = i >> 4, j = i & 15;
      int e = eid_sm[m];
      uint4 A0 = make_uint4(0u,0u,0u,0u), A1 = make_uint4(0u,0u,0u,0u);
      if (e >= 0){
        A0 = s4[(size_t)e * 32 + 2*j];
        A1 = s4[(size_t)e * 32 + 2*j + 1];
      }
      uint4 t0, t1;
      t0.x = to_tf32(__uint_as_float(A0.x)); t0.y = to_tf32(__uint_as_float(A1.x));
      t0.z = to_tf32(__uint_as_float(A0.y)); t0.w = to_tf32(__uint_as_float(A1.y));
      t1.x = to_tf32(__uint_as_float(A0.z)); t1.y = to_tf32(__uint_as_float(A1.z));
      t1.z = to_tf32(__uint_as_float(A0.w)); t1.w = to_tf32(__uint_as_float(A1.w));
      *(uint4*)(su + OFF_S + m*RSTR + 8*j)     = t0;
      *(uint4*)(su + OFF_S + m*RSTR + 8*j + 4) = t1;
    }
  }
  if (tid < TM){
    int e = eid_sm[tid];
    float rxv = 0.f, ryv = 0.f, rzv = 0.f;
    int node = -1;
    if (e >= 0){
      rxv = r_g[3*e+0]; ryv = r_g[3*e+1]; rzv = r_g[3*e+2];
      node = idx_g[e];
    }
    ((int*)(smf + OFF_IDX))[tid] = node;
    float rn = sqrtf(fmaf(rxv,rxv, fmaf(ryv,ryv, rzv*rzv)));
    float invg = smf[OFF_G];
    smf[OFF_RN + tid*4+0] = rxv*invg;
    smf[OFF_RN + tid*4+1] = ryv*invg;
    smf[OFF_RN + tid*4+2] = rzv*invg;
    smf[OFF_RN + tid*4+3] = 0.f;
    if (e >= 0){
      float inv_rn = 1.f / rn;
      const float c0 = 0.62831853071795864769f;  // pi / R_CUT
      #pragma unroll
      for (int k = 0; k < NRBF; k++){
        float t  = sinf((float)(k+1) * c0 * rn) * inv_rn;
        float rb = (t <= 5.0f) ? 0.5f*(cosf(c0*t) + 1.f) : 0.f;
        su[OFF_RBF + tid*20 + k] = to_tf32(rb);
      }
    } else {
      #pragma unroll
      for (int k = 0; k < NRBF; k++) su[OFF_RBF + tid*20 + k] = 0u;
    }
  }
  __syncthreads();

  // ===== chunk c=1 -> P ; epilogue S (run-merged: rows sorted by node) =====
  run_chunk<0>(su, smf, tid, 1, bphi_g, bw_g);
  __syncthreads();
  {
    const int row0 = wid * 8;
    int cur = idx_sm[row0];
    float4 a = *(const float4*)(smf + OFF_P + row0*RSTR + lane*4);
    #pragma unroll
    for (int i = 1; i < 8; i++){
      const int row = row0 + i;
      const int nd  = idx_sm[row];
      float4 v4 = *(const float4*)(smf + OFF_P + row*RSTR + lane*4);
      if (nd == cur){
        a.x += v4.x; a.y += v4.y; a.z += v4.z; a.w += v4.w;
      } else {
        if (cur >= 0) red4(out_s + (size_t)cur*F + lane*4, a.x, a.y, a.z, a.w);
        cur = nd; a = v4;
      }
    }
    if (cur >= 0) red4(out_s + (size_t)cur*F + lane*4, a.x, a.y, a.z, a.w);
  }
  __syncthreads();   // P reads done -> P reusable

  // ===== chunk c=0 -> P (sv) ; chunk c=2 -> regs -> (sync) -> S region (sr) =====
  run_chunk<0>(su, smf, tid, 0, bphi_g, bw_g);
  run_chunk<1>(su, smf, tid, 2, bphi_g, bw_g);   // internal sync before overwriting s tile
  __syncthreads();   // sv (P) and sr (S) both visible

  // ===== epilogue V (run-merged): out_v += sum_run( sv*v + sr*rn ) =====
  {
    const int row0 = wid * 8;
    int cur = -1;
    float4 a0 = make_float4(0.f,0.f,0.f,0.f);
    float4 a1 = make_float4(0.f,0.f,0.f,0.f);
    float4 a2 = make_float4(0.f,0.f,0.f,0.f);
    #pragma unroll
    for (int i = 0; i < 8; i++){
      const int row = row0 + i;
      const int nd  = idx_sm[row];
      if (nd != cur){
        if (cur >= 0){
          float* op = out_v + (size_t)cur * 3*F + lane*4;
          red4(op,         a0.x, a0.y, a0.z, a0.w);
          red4(op + F,     a1.x, a1.y, a1.z, a1.w);
          red4(op + 2*F,   a2.x, a2.y, a2.z, a2.w);
        }
        cur = nd;
        a0 = make_float4(0.f,0.f,0.f,0.f);
        a1 = make_float4(0.f,0.f,0.f,0.f);
        a2 = make_float4(0.f,0.f,0.f,0.f);
      }
      if (nd >= 0){
        const int e = eid_sm[row];
        float4 sv4 = *(const float4*)(smf + OFF_P + row*RSTR + lane*4);
        float4 sr4 = *(const float4*)(smf + OFF_S + row*RSTR + lane*4);
        const float* vp = v_g + (size_t)e * 3*F + lane*4;
        const float r0 = smf[OFF_RN + row*4 + 0];
        const float r1 = smf[OFF_RN + row*4 + 1];
        const float r2 = smf[OFF_RN + row*4 + 2];
        float4 vv;
        vv = *(const float4*)(vp);
        a0.x += fmaf(sv4.x, vv.x, sr4.x*r0); a0.y += fmaf(sv4.y, vv.y, sr4.y*r0);
        a0.z += fmaf(sv4.z, vv.z, sr4.z*r0); a0.w += fmaf(sv4.w, vv.w, sr4.w*r0);
        vv = *(const float4*)(vp + F);
        a1.x += fmaf(sv4.x, vv.x, sr4.x*r1); a1.y += fmaf(sv4.y, vv.y, sr4.y*r1);
        a1.z += fmaf(sv4.z, vv.z, sr4.z*r1); a1.w += fmaf(sv4.w, vv.w, sr4.w*r1);
        vv = *(const float4*)(vp + 2*F);
        a2.x += fmaf(sv4.x, vv.x, sr4.x*r2); a2.y += fmaf(sv4.y, vv.y, sr4.y*r2);
        a2.z += fmaf(sv4.z, vv.z, sr4.z*r2); a2.w += fmaf(sv4.w, vv.w, sr4.w*r2);
      }
    }
    if (cur >= 0){
      float* op = out_v + (size_t)cur * 3*F + lane*4;
      red4(op,       a0.x, a0.y, a0.z, a0.w);
      red4(op + F,   a1.x, a1.y, a1.z, a1.w);
      red4(op + 2*F, a2.x, a2.y, a2.z, a2.w);
    }
  }
}

extern "C" void kernel_launch(void* const* d_in, const int* in_sizes, int n_in,
                              void* d_out, int out_size){
  const float* s_g  = (const float*)d_in[0];
  const float* r_g  = (const float*)d_in[1];
  const float* v_g  = (const float*)d_in[2];
  const int*   idx  = (const int*)  d_in[3];
  const float* Wp   = (const float*)d_in[4];
  const float* bphi = (const float*)d_in[5];
  const float* Ww   = (const float*)d_in[6];
  const float* bw   = (const float*)d_in[7];
  const int E = in_sizes[1] / 3;            // r is (E,3)
  const int N = out_size / (4*F);           // out = out_v (N*3*F) ++ out_s (N*F)
  float* out_v = (float*)d_out;
  float* out_s = out_v + (size_t)N*3*F;

  prep_hist_kernel<<<512, 256>>>(Wp, Ww, r_g, 3*E, idx, E, (float4*)d_out, out_size/4);
  scan_kernel<<<1, 1024>>>(N);
  scatter_kernel<<<512, 256>>>(idx, E, N);
  cudaFuncSetAttribute(fused_message_kernel,
                       cudaFuncAttributeMaxDynamicSharedMemorySize, SMEM_BYTES);
  const int blocks = (E + TM - 1) / TM;
  fused_message_kernel<<<blocks, NTHREADS, SMEM_BYTES>>>(
      s_g, r_g, v_g, idx, bphi, bw, out_v, out_s, E);
}